// round 12
// baseline (speedup 1.0000x reference)
#include <cuda_runtime.h>
#include <cuda_bf16.h>
#include <mma.h>
#include <cstdint>
#include <math.h>

using namespace nvcuda;

#define EPSV 1e-4f
#define BROWS 8192
#define FDIM 512
#define PDIM 64
#define CDIM 100
#define USTRIDE 112

typedef unsigned long long ull;

// ---- device-global scratch ----
__device__ __nv_bfloat16 g_xh[BROWS * FDIM];
__device__ __nv_bfloat16 g_xl[BROWS * FDIM];
__device__ __nv_bfloat16 g_wh[PDIM * FDIM];
__device__ __nv_bfloat16 g_wl[PDIM * FDIM];
__device__ float g_xn[BROWS];
__device__ float g_wn[PDIM];
__device__ float g_si[BROWS * PDIM];
__device__ float g_u2[PDIM * USTRIDE];

// ---- packed f32x2 helpers (scan) ----
__device__ __forceinline__ ull pk2(float lo, float hi) {
    ull r; asm("mov.b64 %0, {%1, %2};" : "=l"(r) : "f"(lo), "f"(hi)); return r;
}
__device__ __forceinline__ float2 upk2(ull v) {
    float2 r; asm("mov.b64 {%0, %1}, %2;" : "=f"(r.x), "=f"(r.y) : "l"(v)); return r;
}
__device__ __forceinline__ ull fma2(ull a, ull b, ull c) {
    ull d; asm("fma.rn.f32x2 %0, %1, %2, %3;" : "=l"(d) : "l"(a), "l"(b), "l"(c)); return d;
}
__device__ __forceinline__ ull mul2(ull a, ull b) {
    ull d; asm("mul.rn.f32x2 %0, %1, %2;" : "=l"(d) : "l"(a), "l"(b)); return d;
}
__device__ __forceinline__ ull add2(ull a, ull b) {
    ull d; asm("add.rn.f32x2 %0, %1, %2;" : "=l"(d) : "l"(a), "l"(b)); return d;
}
__device__ __forceinline__ float frcp(float x) {
    float r; asm("rcp.approx.f32 %0, %1;" : "=f"(r) : "f"(x)); return r;
}
__device__ __forceinline__ unsigned int s2u(const void* p) {
    return (unsigned int)__cvta_generic_to_shared(p);
}
__device__ __forceinline__ void cpa16(unsigned int dst, const void* src) {
    asm volatile("cp.async.cg.shared.global [%0], [%1], 16;" :: "r"(dst), "l"(src));
}

// ================= presplit: bf16 split + norms + u table =================
__device__ __forceinline__ void bsplit(float v, unsigned short& h, unsigned short& l) {
    __nv_bfloat16 hb = __float2bfloat16(v);
    __nv_bfloat16 lb = __float2bfloat16(v - __bfloat162float(hb));
    h = *reinterpret_cast<unsigned short*>(&hb);
    l = *reinterpret_cast<unsigned short*>(&lb);
}

__global__ __launch_bounds__(256)
void presplit_kernel(const float* __restrict__ x, const float* __restrict__ w,
                     const float* __restrict__ beta) {
    const int bid = blockIdx.x, tid = threadIdx.x;
    const int warp = tid >> 5, lane = tid & 31;
    const unsigned FULL = 0xffffffffu;

    if (bid < 256) {
        #pragma unroll
        for (int j = 0; j < 4; j++) {
            int r = bid * 32 + warp * 4 + j;
            const float4* xr = (const float4*)(x + (size_t)r * FDIM);
            ushort4* oh = (ushort4*)(g_xh + (size_t)r * FDIM);
            ushort4* ol = (ushort4*)(g_xl + (size_t)r * FDIM);
            float ss = 0.f;
            #pragma unroll
            for (int i = 0; i < 4; i++) {
                float4 v = __ldg(xr + lane + 32 * i);
                ushort4 H, L;
                bsplit(v.x, H.x, L.x); bsplit(v.y, H.y, L.y);
                bsplit(v.z, H.z, L.z); bsplit(v.w, H.w, L.w);
                oh[lane + 32 * i] = H;
                ol[lane + 32 * i] = L;
                ss += v.x * v.x + v.y * v.y + v.z * v.z + v.w * v.w;
            }
            #pragma unroll
            for (int m = 16; m; m >>= 1) ss += __shfl_xor_sync(FULL, ss, m);
            if (lane == 0) g_xn[r] = ss;
        }
    } else if (bid == 256) {
        #pragma unroll
        for (int j = 0; j < 8; j++) {
            int r = warp * 8 + j;
            const float4* wr = (const float4*)(w + (size_t)r * FDIM);
            ushort4* oh = (ushort4*)(g_wh + (size_t)r * FDIM);
            ushort4* ol = (ushort4*)(g_wl + (size_t)r * FDIM);
            float ss = 0.f;
            #pragma unroll
            for (int i = 0; i < 4; i++) {
                float4 v = __ldg(wr + lane + 32 * i);
                ushort4 H, L;
                bsplit(v.x, H.x, L.x); bsplit(v.y, H.y, L.y);
                bsplit(v.z, H.z, L.z); bsplit(v.w, H.w, L.w);
                oh[lane + 32 * i] = H;
                ol[lane + 32 * i] = L;
                ss += v.x * v.x + v.y * v.y + v.z * v.z + v.w * v.w;
            }
            #pragma unroll
            for (int m = 16; m; m >>= 1) ss += __shfl_xor_sync(FULL, ss, m);
            if (lane == 0) g_wn[r] = ss;
        }
    } else {
        if (tid < PDIM) {
            const float* br = beta + (size_t)tid * CDIM;
            float* ur = g_u2 + tid * USTRIDE;
            float s2 = 0.f;
            #pragma unroll 4
            for (int c = 0; c < CDIM; c++) { float v = br[c]; float bb = v * v; ur[c] = bb; s2 += bb; }
            float rs = 1.f / s2;
            #pragma unroll 4
            for (int c = 0; c < CDIM; c++) ur[c] *= rs;
            #pragma unroll
            for (int c = CDIM; c < USTRIDE; c++) ur[c] = 0.f;
        }
    }
}

// ================= wmma GEMM + si : 64 rows/block, 128 thr, grid 128 ========
// smem bf16 tiles stride 72 (32B-aligned tile bases, ldm mult of 8):
//  sxh @0      : 64*72*2 = 9216 B
//  sxl @9216
//  swh @18432  : 64*72*2 = 9216 B
//  swl @27648
//  consts @36864 : 3*64*4 = 768
//  sOut (f32 64x64) aliases @0 after compute (16384 B)
#define SM_XH 0
#define SM_XL 9216
#define SM_WH 18432
#define SM_WL 27648
#define SM_CON 36864
#define MSM_BYTES 37696
#define BSTR 72

__global__ __launch_bounds__(128)
void mma_si_kernel(const float* __restrict__ xi, const float* __restrict__ eta) {
    extern __shared__ __align__(128) char smem[];
    __nv_bfloat16* sxh = (__nv_bfloat16*)(smem + SM_XH);
    __nv_bfloat16* sxl = (__nv_bfloat16*)(smem + SM_XL);
    __nv_bfloat16* swh = (__nv_bfloat16*)(smem + SM_WH);
    __nv_bfloat16* swl = (__nv_bfloat16*)(smem + SM_WL);
    float* sGam = (float*)(smem + SM_CON);
    float* sAlp = sGam + 64;
    float* sWn  = sAlp + 64;

    const int tid = threadIdx.x;
    const int warp = tid >> 5;
    const int r0 = blockIdx.x * 64;

    if (tid < PDIM) {
        float e = eta[tid];
        sGam[tid] = e * e;
        sAlp[tid] = 1.f / (1.f + __expf(-xi[tid]));
        sWn[tid]  = g_wn[tid];
    }

    wmma::fragment<wmma::accumulator, 16, 16, 16, float> acc[4];
    #pragma unroll
    for (int nt = 0; nt < 4; nt++) wmma::fill_fragment(acc[nt], 0.f);

    #pragma unroll 1
    for (int ch = 0; ch < FDIM / 64; ch++) {
        // stage 64x64 x-tiles and 64x64 w-tiles (h+l), 16B transfers
        #pragma unroll
        for (int it = 0; it < 4; it++) {
            int f = tid + it * 128;
            int row = f >> 3, c16 = f & 7;
            unsigned off = row * (BSTR * 2) + c16 * 16;
            size_t gx = (size_t)(r0 + row) * FDIM + ch * 64 + c16 * 8;
            size_t gw = (size_t)row * FDIM + ch * 64 + c16 * 8;
            cpa16(s2u(smem + SM_XH + off), g_xh + gx);
            cpa16(s2u(smem + SM_XL + off), g_xl + gx);
            cpa16(s2u(smem + SM_WH + off), g_wh + gw);
            cpa16(s2u(smem + SM_WL + off), g_wl + gw);
        }
        asm volatile("cp.async.commit_group;" ::: "memory");
        asm volatile("cp.async.wait_group 0;" ::: "memory");
        __syncthreads();

        #pragma unroll
        for (int kk = 0; kk < 4; kk++) {
            wmma::fragment<wmma::matrix_a, 16, 16, 16, __nv_bfloat16, wmma::row_major> ah, al;
            wmma::load_matrix_sync(ah, sxh + warp * 16 * BSTR + kk * 16, BSTR);
            wmma::load_matrix_sync(al, sxl + warp * 16 * BSTR + kk * 16, BSTR);
            #pragma unroll
            for (int nt = 0; nt < 4; nt++) {
                wmma::fragment<wmma::matrix_b, 16, 16, 16, __nv_bfloat16, wmma::col_major> bh, bl;
                wmma::load_matrix_sync(bh, swh + nt * 16 * BSTR + kk * 16, BSTR);
                wmma::load_matrix_sync(bl, swl + nt * 16 * BSTR + kk * 16, BSTR);
                wmma::mma_sync(acc[nt], ah, bh, acc[nt]);
                wmma::mma_sync(acc[nt], ah, bl, acc[nt]);
                wmma::mma_sync(acc[nt], al, bh, acc[nt]);
            }
        }
        __syncthreads();
    }

    // dump accumulators to smem (aliases x tiles; synced above)
    float* sO = (float*)(smem + SM_XH);
    #pragma unroll
    for (int nt = 0; nt < 4; nt++)
        wmma::store_matrix_sync(sO + warp * 16 * 64 + nt * 16, acc[nt], 64, wmma::mem_row_major);
    __syncthreads();

    // epilogue: one thread per row
    if (tid < 64) {
        const int row = r0 + tid;
        const float xn = __ldg(g_xn + row);
        const float* dr = sO + tid * 64;
        float sv[64];
        float mx = 0.f;
        #pragma unroll
        for (int p = 0; p < PDIM; p++) {
            float d = xn - 2.f * dr[p] + sWn[p];
            float s = __expf(-sGam[p] * d) * sAlp[p];
            sv[p] = s;
            mx = fmaxf(mx, s);
        }
        float inv = 1.f / (mx + EPSV);
        float* orow = g_si + (size_t)row * PDIM;
        #pragma unroll
        for (int p4 = 0; p4 < PDIM; p4 += 4) {
            float4 o;
            o.x = sv[p4 + 0] * inv; o.y = sv[p4 + 1] * inv;
            o.z = sv[p4 + 2] * inv; o.w = sv[p4 + 3] * inv;
            *(float4*)(orow + p4) = o;
        }
    }
}

// ================= Dempster scan : R9 verbatim =================
#define SSM_FLOATS (7168 + 32 * 68 + 32 * 102)

#define DS_STEP(P, APPLY, START) do {                                          \
    float sA_ = srowA[(P)], sB_ = srowB[(P)];                                  \
    float aA_ = 1.f - sA_,  aB_ = 1.f - sB_;                                   \
    if (APPLY) { sA_ *= pendA; aA_ *= pendA; sB_ *= pendB; aB_ *= pendB; }     \
    float g1A_ = sA_ * omA, g1B_ = sB_ * omB;                                  \
    omA = 3.f * aA_ * omA;  omB = 3.f * aB_ * omB;                             \
    ull spA_ = pk2(sA_, sA_), apA_ = pk2(aA_, aA_), gpA_ = pk2(g1A_, g1A_);    \
    ull spB_ = pk2(sB_, sB_), apB_ = pk2(aB_, aB_), gpB_ = pk2(g1B_, g1B_);    \
    const float* up_ = sU + (P) * USTRIDE + 2 * q;                             \
    _Pragma("unroll")                                                          \
    for (int i_ = 0; i_ < 7; i_++) {                                           \
        ull u2_ = *(const ull*)(up_ + 16 * i_);                                \
        mA[i_] = fma2(gpA_, u2_, mul2(mA[i_], fma2(spA_, u2_, apA_)));         \
        mB[i_] = fma2(gpB_, u2_, mul2(mB[i_], fma2(spB_, u2_, apB_)));         \
    }                                                                          \
    if (START) {                                                               \
        ull psA_ = mA[0], psB_ = mB[0];                                        \
        _Pragma("unroll")                                                      \
        for (int i_ = 1; i_ < 7; i_++) { psA_ = add2(psA_, mA[i_]); psB_ = add2(psB_, mB[i_]); } \
        float2 va_ = upk2(psA_), vb_ = upk2(psB_);                             \
        float pa_ = va_.x + va_.y, pb_ = vb_.x + vb_.y;                        \
        pa_ += __shfl_xor_sync(FULL, pa_, 1); pb_ += __shfl_xor_sync(FULL, pb_, 1); \
        pa_ += __shfl_xor_sync(FULL, pa_, 2); pb_ += __shfl_xor_sync(FULL, pb_, 2); \
        pa_ += __shfl_xor_sync(FULL, pa_, 4); pb_ += __shfl_xor_sync(FULL, pb_, 4); \
        pendA = frcp(pa_ + omA); pendB = frcp(pb_ + omB);                      \
    }                                                                          \
} while (0)

__global__ __launch_bounds__(128)
void scan_kernel(float* __restrict__ out) {
    extern __shared__ __align__(16) float ssm[];
    float* sU   = ssm;
    float* sSi  = ssm + 7168;
    float* sOut = ssm + 7168 + 32 * 68;

    const int tid = threadIdx.x;
    const int r0  = blockIdx.x * 32;
    const unsigned FULL = 0xffffffffu;

    #pragma unroll
    for (int it = 0; it < 14; it++) {
        int f = tid + it * 128;
        *(float4*)(sU + f * 4) = *(const float4*)(g_u2 + f * 4);
    }
    #pragma unroll
    for (int it = 0; it < 4; it++) {
        int f = tid + it * 128;
        int r = f >> 4, c = f & 15;
        *(float4*)(sSi + r * 68 + c * 4) =
            *(const float4*)(g_si + (size_t)(r0 + r) * PDIM + c * 4);
    }
    __syncthreads();

    const int lane = tid & 31;
    const int warp = tid >> 5;
    const int g = lane >> 3;
    const int q = lane & 7;
    const int rA = warp * 8 + g * 2;
    const int rB = rA + 1;
    const float* srowA = sSi + rA * 68;
    const float* srowB = sSi + rB * 68;

    ull mA[7], mB[7];
    float omA, omB, pendA = 1.f, pendB = 1.f;
    {
        float s0A = srowA[0], s0B = srowB[0];
        ull sA0 = pk2(s0A, s0A), sB0 = pk2(s0B, s0B);
        const float* u0 = sU + 2 * q;
        #pragma unroll
        for (int i = 0; i < 7; i++) {
            ull u2 = *(const ull*)(u0 + 16 * i);
            mA[i] = mul2(sA0, u2);
            mB[i] = mul2(sB0, u2);
        }
        omA = 1.f - s0A; omB = 1.f - s0B;
    }

    DS_STEP(1, false, false);
    DS_STEP(2, false, true);
    #pragma unroll 1
    for (int k = 0; k < 15; k++) {
        int p = 3 + (k << 2);
        DS_STEP(p,     false, false);
        DS_STEP(p + 1, true,  false);
        DS_STEP(p + 2, false, false);
        DS_STEP(p + 3, false, true);
    }
    DS_STEP(63, false, false);

    {
        ull psA = mA[0], psB = mB[0];
        #pragma unroll
        for (int i = 1; i < 7; i++) { psA = add2(psA, mA[i]); psB = add2(psB, mB[i]); }
        float2 va = upk2(psA), vb = upk2(psB);
        float fa = va.x + va.y, fb = vb.x + vb.y;
        fa += __shfl_xor_sync(FULL, fa, 1); fb += __shfl_xor_sync(FULL, fb, 1);
        fa += __shfl_xor_sync(FULL, fa, 2); fb += __shfl_xor_sync(FULL, fb, 2);
        fa += __shfl_xor_sync(FULL, fa, 4); fb += __shfl_xor_sync(FULL, fb, 4);
        float rnA = 1.f / (fa + omA), rnB = 1.f / (fb + omB);

        float* oA = sOut + rA * 102;
        float* oB = sOut + rB * 102;
        #pragma unroll
        for (int i = 0; i < 6; i++) {
            int j = 2 * q + 16 * i;
            float2 a = upk2(mA[i]), b = upk2(mB[i]);
            *(float2*)(oA + j) = make_float2(a.x * rnA, a.y * rnA);
            *(float2*)(oB + j) = make_float2(b.x * rnB, b.y * rnB);
        }
        int j = 96 + 2 * q;
        if (q < 2) {
            float2 a = upk2(mA[6]), b = upk2(mB[6]);
            *(float2*)(oA + j) = make_float2(a.x * rnA, a.y * rnA);
            *(float2*)(oB + j) = make_float2(b.x * rnB, b.y * rnB);
        } else if (q == 2) {
            oA[100] = omA * rnA;
            oB[100] = omB * rnB;
        }
    }
    __syncthreads();

    for (int idx = tid; idx < 32 * (CDIM + 1); idx += 128) {
        int rr = idx / (CDIM + 1);
        int jj = idx - rr * (CDIM + 1);
        out[(size_t)r0 * (CDIM + 1) + idx] = sOut[rr * 102 + jj];
    }
}

extern "C" void kernel_launch(void* const* d_in, const int* in_sizes, int n_in,
                              void* d_out, int out_size) {
    const float* x    = (const float*)d_in[0];
    const float* w    = (const float*)d_in[1];
    const float* xi   = (const float*)d_in[2];
    const float* eta  = (const float*)d_in[3];
    const float* beta = (const float*)d_in[4];
    float* out = (float*)d_out;

    cudaFuncSetAttribute(mma_si_kernel,
                         cudaFuncAttributeMaxDynamicSharedMemorySize, MSM_BYTES);
    cudaFuncSetAttribute(scan_kernel,
                         cudaFuncAttributeMaxDynamicSharedMemorySize, SSM_FLOATS * 4);

    presplit_kernel<<<258, 256>>>(x, w, beta);
    mma_si_kernel<<<BROWS / 64, 128, MSM_BYTES>>>(xi, eta);
    scan_kernel<<<BROWS / 32, 128, SSM_FLOATS * 4>>>(out);
}

// round 13
// speedup vs baseline: 1.4264x; 1.4264x over previous
#include <cuda_runtime.h>
#include <cuda_bf16.h>
#include <mma.h>
#include <cstdint>
#include <math.h>

using namespace nvcuda;

#define EPSV 1e-4f
#define BROWS 8192
#define FDIM 512
#define PDIM 64
#define CDIM 100
#define USTRIDE 112

typedef unsigned long long ull;

__device__ float g_si[BROWS * PDIM];
__device__ float g_u2[PDIM * USTRIDE];

// ---- packed f32x2 helpers (scan) ----
__device__ __forceinline__ ull pk2(float lo, float hi) {
    ull r; asm("mov.b64 %0, {%1, %2};" : "=l"(r) : "f"(lo), "f"(hi)); return r;
}
__device__ __forceinline__ float2 upk2(ull v) {
    float2 r; asm("mov.b64 {%0, %1}, %2;" : "=f"(r.x), "=f"(r.y) : "l"(v)); return r;
}
__device__ __forceinline__ ull fma2(ull a, ull b, ull c) {
    ull d; asm("fma.rn.f32x2 %0, %1, %2, %3;" : "=l"(d) : "l"(a), "l"(b), "l"(c)); return d;
}
__device__ __forceinline__ ull mul2(ull a, ull b) {
    ull d; asm("mul.rn.f32x2 %0, %1, %2;" : "=l"(d) : "l"(a), "l"(b)); return d;
}
__device__ __forceinline__ ull add2(ull a, ull b) {
    ull d; asm("add.rn.f32x2 %0, %1, %2;" : "=l"(d) : "l"(a), "l"(b)); return d;
}
__device__ __forceinline__ float frcp(float x) {
    float r; asm("rcp.approx.f32 %0, %1;" : "=f"(r) : "f"(x)); return r;
}
__device__ __forceinline__ unsigned int s2u(const void* p) {
    return (unsigned int)__cvta_generic_to_shared(p);
}
__device__ __forceinline__ void cpa16(unsigned int dst, const void* src) {
    asm volatile("cp.async.cg.shared.global [%0], [%1], 16;" :: "r"(dst), "l"(src));
}
__device__ __forceinline__ void bsplit(float v, unsigned short& h, unsigned short& l) {
    __nv_bfloat16 hb = __float2bfloat16(v);
    __nv_bfloat16 lb = __float2bfloat16(v - __bfloat162float(hb));
    h = *reinterpret_cast<unsigned short*>(&hb);
    l = *reinterpret_cast<unsigned short*>(&lb);
}

// ================= fused split + wmma GEMM + si =================
// 64 rows/block, 128 thr, grid 129 (block 128 = u table).
// smem (bytes):
//   stage fp32 @0       : 2 bufs x (x 16384 + w 16384) = 65536
//   sxh @65536, sxl @74752, swh @83968, swl @93184 (bf16 tiles, stride 72)
//   consts @102400 : sGam 256 | sAlp 256 | sWn 256 | sXn 256
//   sO (f32 64x64) aliases stage @0
#define SM_XH 65536
#define SM_XL 74752
#define SM_WH 83968
#define SM_WL 93184
#define SM_CON 102400
#define MSM_BYTES 103424
#define BSTR 72

__global__ __launch_bounds__(128)
void mma_si_kernel(const float* __restrict__ x, const float* __restrict__ w,
                   const float* __restrict__ xi, const float* __restrict__ eta,
                   const float* __restrict__ beta) {
    extern __shared__ __align__(128) char smem[];
    const int tid = threadIdx.x;

    // block 128: u table
    if (blockIdx.x == 128) {
        if (tid < PDIM) {
            const float* br = beta + (size_t)tid * CDIM;
            float* ur = g_u2 + tid * USTRIDE;
            float s2 = 0.f;
            #pragma unroll 4
            for (int c = 0; c < CDIM; c++) { float v = br[c]; float bb = v * v; ur[c] = bb; s2 += bb; }
            float rs = 1.f / s2;
            #pragma unroll 4
            for (int c = 0; c < CDIM; c++) ur[c] *= rs;
            #pragma unroll
            for (int c = CDIM; c < USTRIDE; c++) ur[c] = 0.f;
        }
        return;
    }

    float* dsmf = (float*)smem;
    __nv_bfloat16* sxh = (__nv_bfloat16*)(smem + SM_XH);
    __nv_bfloat16* sxl = (__nv_bfloat16*)(smem + SM_XL);
    __nv_bfloat16* swh = (__nv_bfloat16*)(smem + SM_WH);
    __nv_bfloat16* swl = (__nv_bfloat16*)(smem + SM_WL);
    float* sGam = (float*)(smem + SM_CON);
    float* sAlp = sGam + 64;
    float* sWn  = sAlp + 64;
    float* sXn  = sWn + 64;

    const int warp = tid >> 5;
    const int r0 = blockIdx.x * 64;
    const unsigned FULL = 0xffffffffu;

    if (tid < PDIM) {
        float e = eta[tid];
        sGam[tid] = e * e;
        sAlp[tid] = 1.f / (1.f + __expf(-xi[tid]));
    }

    // stage chunk 0 (fp32 x + w)
    {
        #pragma unroll
        for (int it = 0; it < 8; it++) {
            int f = tid + it * 128;
            int row = f >> 4, c4 = (f & 15) << 2;
            cpa16(s2u(smem + f * 16), x + (size_t)(r0 + row) * FDIM + c4);
            cpa16(s2u(smem + 16384 + f * 16), w + (size_t)row * FDIM + c4);
        }
        asm volatile("cp.async.commit_group;" ::: "memory");
    }

    wmma::fragment<wmma::accumulator, 16, 16, 16, float> acc[4];
    #pragma unroll
    for (int nt = 0; nt < 4; nt++) wmma::fill_fragment(acc[nt], 0.f);

    float xnp[8] = {0.f,0.f,0.f,0.f,0.f,0.f,0.f,0.f};
    float wnp[8] = {0.f,0.f,0.f,0.f,0.f,0.f,0.f,0.f};

    #pragma unroll 1
    for (int ch = 0; ch < FDIM / 64; ch++) {
        const int buf = ch & 1;
        asm volatile("cp.async.wait_group 0;" ::: "memory");
        __syncthreads();   // staging[buf] ready AND tiles free (prev mma done)

        // kick off next chunk's staging (overlaps conversion + mma)
        if (ch < FDIM / 64 - 1) {
            const int nb = buf ^ 1;
            #pragma unroll
            for (int it = 0; it < 8; it++) {
                int f = tid + it * 128;
                int row = f >> 4, c4 = (f & 15) << 2;
                int kc = (ch + 1) * 64;
                cpa16(s2u(smem + nb * 32768 + f * 16),
                      x + (size_t)(r0 + row) * FDIM + kc + c4);
                cpa16(s2u(smem + nb * 32768 + 16384 + f * 16),
                      w + (size_t)row * FDIM + kc + c4);
            }
            asm volatile("cp.async.commit_group;" ::: "memory");
        }

        // convert fp32 staging -> bf16 h/l tiles; accumulate norm partials
        const float* sxf = dsmf + buf * 8192;
        const float* swf = sxf + 4096;
        #pragma unroll
        for (int it = 0; it < 8; it++) {
            int f = tid + it * 128;
            int row = f >> 4, c = (f & 15) << 2;
            float4 v = *(const float4*)(sxf + f * 4);
            ushort4 H, L;
            bsplit(v.x, H.x, L.x); bsplit(v.y, H.y, L.y);
            bsplit(v.z, H.z, L.z); bsplit(v.w, H.w, L.w);
            *(ushort4*)(sxh + row * BSTR + c) = H;
            *(ushort4*)(sxl + row * BSTR + c) = L;
            xnp[it] += v.x * v.x + v.y * v.y + v.z * v.z + v.w * v.w;

            float4 u = *(const float4*)(swf + f * 4);
            bsplit(u.x, H.x, L.x); bsplit(u.y, H.y, L.y);
            bsplit(u.z, H.z, L.z); bsplit(u.w, H.w, L.w);
            *(ushort4*)(swh + row * BSTR + c) = H;
            *(ushort4*)(swl + row * BSTR + c) = L;
            wnp[it] += u.x * u.x + u.y * u.y + u.z * u.z + u.w * u.w;
        }
        __syncthreads();   // tiles ready

        #pragma unroll
        for (int kk = 0; kk < 4; kk++) {
            wmma::fragment<wmma::matrix_a, 16, 16, 16, __nv_bfloat16, wmma::row_major> ah, al;
            wmma::load_matrix_sync(ah, sxh + warp * 16 * BSTR + kk * 16, BSTR);
            wmma::load_matrix_sync(al, sxl + warp * 16 * BSTR + kk * 16, BSTR);
            #pragma unroll
            for (int nt = 0; nt < 4; nt++) {
                wmma::fragment<wmma::matrix_b, 16, 16, 16, __nv_bfloat16, wmma::col_major> bh, bl;
                wmma::load_matrix_sync(bh, swh + nt * 16 * BSTR + kk * 16, BSTR);
                wmma::load_matrix_sync(bl, swl + nt * 16 * BSTR + kk * 16, BSTR);
                wmma::mma_sync(acc[nt], ah, bh, acc[nt]);
                wmma::mma_sync(acc[nt], ah, bl, acc[nt]);
                wmma::mma_sync(acc[nt], al, bh, acc[nt]);
            }
        }
        // loop-top sync protects tiles from next conversion
    }

    // reduce norm partials: row (tid>>4)+8*it owned by 16 consecutive tids
    #pragma unroll
    for (int it = 0; it < 8; it++) {
        float vx = xnp[it], vw = wnp[it];
        vx += __shfl_xor_sync(FULL, vx, 1); vw += __shfl_xor_sync(FULL, vw, 1);
        vx += __shfl_xor_sync(FULL, vx, 2); vw += __shfl_xor_sync(FULL, vw, 2);
        vx += __shfl_xor_sync(FULL, vx, 4); vw += __shfl_xor_sync(FULL, vw, 4);
        vx += __shfl_xor_sync(FULL, vx, 8); vw += __shfl_xor_sync(FULL, vw, 8);
        if ((tid & 15) == 0) {
            int r = (tid >> 4) + 8 * it;
            sXn[r] = vx;
            sWn[r] = vw;
        }
    }
    __syncthreads();

    // dump accumulators to smem (aliases staging)
    float* sO = dsmf;
    #pragma unroll
    for (int nt = 0; nt < 4; nt++)
        wmma::store_matrix_sync(sO + warp * 16 * 64 + nt * 16, acc[nt], 64, wmma::mem_row_major);
    __syncthreads();

    // epilogue: one thread per row
    if (tid < 64) {
        const int row = r0 + tid;
        const float xn = sXn[tid];
        const float* dr = sO + tid * 64;
        float sv[64];
        float mx = 0.f;
        #pragma unroll
        for (int p = 0; p < PDIM; p++) {
            float d = xn - 2.f * dr[p] + sWn[p];
            float s = __expf(-sGam[p] * d) * sAlp[p];
            sv[p] = s;
            mx = fmaxf(mx, s);
        }
        float inv = 1.f / (mx + EPSV);
        float* orow = g_si + (size_t)row * PDIM;
        #pragma unroll
        for (int p4 = 0; p4 < PDIM; p4 += 4) {
            float4 o;
            o.x = sv[p4 + 0] * inv; o.y = sv[p4 + 1] * inv;
            o.z = sv[p4 + 2] * inv; o.w = sv[p4 + 3] * inv;
            *(float4*)(orow + p4) = o;
        }
    }
}

// ================= Dempster scan : R9 verbatim =================
#define SSM_FLOATS (7168 + 32 * 68 + 32 * 102)

#define DS_STEP(P, APPLY, START) do {                                          \
    float sA_ = srowA[(P)], sB_ = srowB[(P)];                                  \
    float aA_ = 1.f - sA_,  aB_ = 1.f - sB_;                                   \
    if (APPLY) { sA_ *= pendA; aA_ *= pendA; sB_ *= pendB; aB_ *= pendB; }     \
    float g1A_ = sA_ * omA, g1B_ = sB_ * omB;                                  \
    omA = 3.f * aA_ * omA;  omB = 3.f * aB_ * omB;                             \
    ull spA_ = pk2(sA_, sA_), apA_ = pk2(aA_, aA_), gpA_ = pk2(g1A_, g1A_);    \
    ull spB_ = pk2(sB_, sB_), apB_ = pk2(aB_, aB_), gpB_ = pk2(g1B_, g1B_);    \
    const float* up_ = sU + (P) * USTRIDE + 2 * q;                             \
    _Pragma("unroll")                                                          \
    for (int i_ = 0; i_ < 7; i_++) {                                           \
        ull u2_ = *(const ull*)(up_ + 16 * i_);                                \
        mA[i_] = fma2(gpA_, u2_, mul2(mA[i_], fma2(spA_, u2_, apA_)));         \
        mB[i_] = fma2(gpB_, u2_, mul2(mB[i_], fma2(spB_, u2_, apB_)));         \
    }                                                                          \
    if (START) {                                                               \
        ull psA_ = mA[0], psB_ = mB[0];                                        \
        _Pragma("unroll")                                                      \
        for (int i_ = 1; i_ < 7; i_++) { psA_ = add2(psA_, mA[i_]); psB_ = add2(psB_, mB[i_]); } \
        float2 va_ = upk2(psA_), vb_ = upk2(psB_);                             \
        float pa_ = va_.x + va_.y, pb_ = vb_.x + vb_.y;                        \
        pa_ += __shfl_xor_sync(FULL, pa_, 1); pb_ += __shfl_xor_sync(FULL, pb_, 1); \
        pa_ += __shfl_xor_sync(FULL, pa_, 2); pb_ += __shfl_xor_sync(FULL, pb_, 2); \
        pa_ += __shfl_xor_sync(FULL, pa_, 4); pb_ += __shfl_xor_sync(FULL, pb_, 4); \
        pendA = frcp(pa_ + omA); pendB = frcp(pb_ + omB);                      \
    }                                                                          \
} while (0)

__global__ __launch_bounds__(128)
void scan_kernel(float* __restrict__ out) {
    extern __shared__ __align__(16) float ssm[];
    float* sU   = ssm;
    float* sSi  = ssm + 7168;
    float* sOut = ssm + 7168 + 32 * 68;

    const int tid = threadIdx.x;
    const int r0  = blockIdx.x * 32;
    const unsigned FULL = 0xffffffffu;

    #pragma unroll
    for (int it = 0; it < 14; it++) {
        int f = tid + it * 128;
        *(float4*)(sU + f * 4) = *(const float4*)(g_u2 + f * 4);
    }
    #pragma unroll
    for (int it = 0; it < 4; it++) {
        int f = tid + it * 128;
        int r = f >> 4, c = f & 15;
        *(float4*)(sSi + r * 68 + c * 4) =
            *(const float4*)(g_si + (size_t)(r0 + r) * PDIM + c * 4);
    }
    __syncthreads();

    const int lane = tid & 31;
    const int warp = tid >> 5;
    const int g = lane >> 3;
    const int q = lane & 7;
    const int rA = warp * 8 + g * 2;
    const int rB = rA + 1;
    const float* srowA = sSi + rA * 68;
    const float* srowB = sSi + rB * 68;

    ull mA[7], mB[7];
    float omA, omB, pendA = 1.f, pendB = 1.f;
    {
        float s0A = srowA[0], s0B = srowB[0];
        ull sA0 = pk2(s0A, s0A), sB0 = pk2(s0B, s0B);
        const float* u0 = sU + 2 * q;
        #pragma unroll
        for (int i = 0; i < 7; i++) {
            ull u2 = *(const ull*)(u0 + 16 * i);
            mA[i] = mul2(sA0, u2);
            mB[i] = mul2(sB0, u2);
        }
        omA = 1.f - s0A; omB = 1.f - s0B;
    }

    DS_STEP(1, false, false);
    DS_STEP(2, false, true);
    #pragma unroll 1
    for (int k = 0; k < 15; k++) {
        int p = 3 + (k << 2);
        DS_STEP(p,     false, false);
        DS_STEP(p + 1, true,  false);
        DS_STEP(p + 2, false, false);
        DS_STEP(p + 3, false, true);
    }
    DS_STEP(63, false, false);

    {
        ull psA = mA[0], psB = mB[0];
        #pragma unroll
        for (int i = 1; i < 7; i++) { psA = add2(psA, mA[i]); psB = add2(psB, mB[i]); }
        float2 va = upk2(psA), vb = upk2(psB);
        float fa = va.x + va.y, fb = vb.x + vb.y;
        fa += __shfl_xor_sync(FULL, fa, 1); fb += __shfl_xor_sync(FULL, fb, 1);
        fa += __shfl_xor_sync(FULL, fa, 2); fb += __shfl_xor_sync(FULL, fb, 2);
        fa += __shfl_xor_sync(FULL, fa, 4); fb += __shfl_xor_sync(FULL, fb, 4);
        float rnA = 1.f / (fa + omA), rnB = 1.f / (fb + omB);

        float* oA = sOut + rA * 102;
        float* oB = sOut + rB * 102;
        #pragma unroll
        for (int i = 0; i < 6; i++) {
            int j = 2 * q + 16 * i;
            float2 a = upk2(mA[i]), b = upk2(mB[i]);
            *(float2*)(oA + j) = make_float2(a.x * rnA, a.y * rnA);
            *(float2*)(oB + j) = make_float2(b.x * rnB, b.y * rnB);
        }
        int j = 96 + 2 * q;
        if (q < 2) {
            float2 a = upk2(mA[6]), b = upk2(mB[6]);
            *(float2*)(oA + j) = make_float2(a.x * rnA, a.y * rnA);
            *(float2*)(oB + j) = make_float2(b.x * rnB, b.y * rnB);
        } else if (q == 2) {
            oA[100] = omA * rnA;
            oB[100] = omB * rnB;
        }
    }
    __syncthreads();

    for (int idx = tid; idx < 32 * (CDIM + 1); idx += 128) {
        int rr = idx / (CDIM + 1);
        int jj = idx - rr * (CDIM + 1);
        out[(size_t)r0 * (CDIM + 1) + idx] = sOut[rr * 102 + jj];
    }
}

extern "C" void kernel_launch(void* const* d_in, const int* in_sizes, int n_in,
                              void* d_out, int out_size) {
    const float* x    = (const float*)d_in[0];
    const float* w    = (const float*)d_in[1];
    const float* xi   = (const float*)d_in[2];
    const float* eta  = (const float*)d_in[3];
    const float* beta = (const float*)d_in[4];
    float* out = (float*)d_out;

    cudaFuncSetAttribute(mma_si_kernel,
                         cudaFuncAttributeMaxDynamicSharedMemorySize, MSM_BYTES);
    cudaFuncSetAttribute(scan_kernel,
                         cudaFuncAttributeMaxDynamicSharedMemorySize, SSM_FLOATS * 4);

    mma_si_kernel<<<BROWS / 64 + 1, 128, MSM_BYTES>>>(x, w, xi, eta, beta);
    scan_kernel<<<BROWS / 32, 128, SSM_FLOATS * 4>>>(out);
}